// round 12
// baseline (speedup 1.0000x reference)
#include <cuda_runtime.h>
#include <cuda_bf16.h>
#include <cstdint>

#define B_ 64
#define N_ 197
#define C_ 768
#define H_ 12
#define DH_ 64
#define M_ (B_*N_)          // 12608
#define NN_ (N_*N_)         // 38809
#define NUM_REL_ 732
#define QSCALE 0.125f
#define KP_ 2304            // packed K = 3*768
#define NCH_ 36             // K chunks of 64 bf16
#define SROW 72             // smem row stride in bf16 (64 + 8 pad)
#define SA_ (128*SROW*2)    // one smem tile: 18432 bytes
#define SKR 68              // scores smem row stride in floats (64 + 4 pad)

// ---------------- scratch ----------------
__device__ float g_q[(size_t)B_*H_*N_*DH_];
__device__ float g_k[(size_t)B_*H_*N_*DH_];
__device__ float g_v[(size_t)B_*H_*N_*DH_];
__device__ float g_attn [(size_t)B_*H_*NN_];
__device__ float g_attn2[(size_t)B_*H_*NN_];
__device__ __nv_bfloat16 g_apack[(size_t)M_*KP_];     // packed activations [hi,hi,lo]
__device__ __nv_bfloat16 g_bqkv [(size_t)3*C_*KP_];   // packed qkv weights [hi,lo,hi]
__device__ __nv_bfloat16 g_bproj[(size_t)C_*KP_];     // packed proj weights

// ---------------- PTX helpers (baseline ISA only) ----------------
__device__ __forceinline__ uint32_t smem_to_u32(const void* p) {
    uint32_t a;
    asm("{ .reg .u64 t; cvta.to.shared.u64 t, %1; cvt.u32.u64 %0, t; }" : "=r"(a) : "l"(p));
    return a;
}
#define CP_ASYNC16(sm, gp) \
    asm volatile("cp.async.cg.shared.global [%0], [%1], 16;" :: "r"(sm), "l"(gp))
#define CP_COMMIT()  asm volatile("cp.async.commit_group;" ::: "memory")
#define CP_WAIT0()   asm volatile("cp.async.wait_group 0;" ::: "memory")
#define LDSM_X4(r0,r1,r2,r3, addr) \
    asm volatile("ldmatrix.sync.aligned.m8n8.x4.shared.b16 {%0,%1,%2,%3}, [%4];" \
        : "=r"(r0), "=r"(r1), "=r"(r2), "=r"(r3) : "r"(addr))

__device__ __forceinline__ void mma16816(float* c, const uint32_t* a, uint32_t b0, uint32_t b1) {
    asm volatile("mma.sync.aligned.m16n8k16.row.col.f32.bf16.bf16.f32 "
        "{%0,%1,%2,%3}, {%4,%5,%6,%7}, {%8,%9}, {%0,%1,%2,%3};"
        : "+f"(c[0]), "+f"(c[1]), "+f"(c[2]), "+f"(c[3])
        : "r"(a[0]), "r"(a[1]), "r"(a[2]), "r"(a[3]), "r"(b0), "r"(b1));
}

// FMA-pipeline exp. x <= 0 expected; clamped at -80.
__device__ __forceinline__ float fast_expf(float x) {
    x = fmaxf(x, -80.f);
    float y = fmaf(x, 1.44269504f, 12582912.0f);
    int   ni = __float_as_int(y);
    float n  = y - 12582912.0f;
    float f  = fmaf(x, 1.44269504f, -n);
    float p  = fmaf(f, 0.00133336f, 0.00961813f);
    p = fmaf(f, p, 0.05550411f);
    p = fmaf(f, p, 0.24022651f);
    p = fmaf(f, p, 0.69314718f);
    p = fmaf(f, p, 1.0f);
    float s = __int_as_float((ni << 23) + 0x3f800000);
    return p * s;
}

// =====================================================================
// Pack kernels: f32 -> split bf16 along packed K
// =====================================================================
__global__ __launch_bounds__(256) void pack_a(const float* __restrict__ src,
                                              __nv_bfloat16* __restrict__ dst, int total)
{
    int idx = blockIdx.x * 256 + threadIdx.x;
    if (idx >= total) return;
    int row = idx / C_, k = idx - row * C_;
    float v = src[idx];
    __nv_bfloat16 hi = __float2bfloat16(v);
    __nv_bfloat16 lo = __float2bfloat16(v - __bfloat162float(hi));
    size_t ro = (size_t)row * KP_;
    dst[ro + k] = hi; dst[ro + C_ + k] = hi; dst[ro + 2*C_ + k] = lo;
}
__global__ __launch_bounds__(256) void pack_b(const float* __restrict__ src,
                                              __nv_bfloat16* __restrict__ dst, int total)
{
    int idx = blockIdx.x * 256 + threadIdx.x;
    if (idx >= total) return;
    int row = idx / C_, k = idx - row * C_;
    float v = src[idx];
    __nv_bfloat16 hi = __float2bfloat16(v);
    __nv_bfloat16 lo = __float2bfloat16(v - __bfloat162float(hi));
    size_t ro = (size_t)row * KP_;
    dst[ro + k] = hi; dst[ro + C_ + k] = lo; dst[ro + 2*C_ + k] = hi;
}

// =====================================================================
// mma.sync GEMM (proven shape): block 128x128, 8 warps (2Mx4N),
// warp tile 64x32, BK=64, double-buffered cp.async, 2 CTAs/SM.
// MODE 0: qkv epilogue (q,k,v -> f32); MODE 1: proj epilogue -> out.
// =====================================================================
template<int MODE>
__global__ __launch_bounds__(256) void tc_gemm(
    const __nv_bfloat16* __restrict__ Ap, const __nv_bfloat16* __restrict__ Bp,
    const float* __restrict__ p_qb, const float* __restrict__ p_vb,
    const float* __restrict__ sscale, const float* __restrict__ sshift,
    float* __restrict__ outp)
{
    extern __shared__ char smem_raw[];
    const uint32_t sbase = smem_to_u32(smem_raw);
    const int tid = threadIdx.x;
    const int lane = tid & 31, wid = tid >> 5;
    const int wm = wid & 1;
    const int wn = wid >> 1;
    const int row0 = blockIdx.x * 128;
    const int col0 = blockIdx.y * 128;

    const int lcol = tid & 7;
    const int lrow = tid >> 3;
    const __nv_bfloat16* agp[4];
    const __nv_bfloat16* bgp[4];
#pragma unroll
    for (int u = 0; u < 4; u++) {
        int ar = min(row0 + lrow + u * 32, M_ - 1);
        agp[u] = Ap + (size_t)ar * KP_ + lcol * 8;
        bgp[u] = Bp + (size_t)(col0 + lrow + u * 32) * KP_ + lcol * 8;
    }
    const uint32_t ssto = (uint32_t)((lrow * SROW + lcol * 8) * 2);

    auto load_chunk = [&](int ch, int bsel) {
        const uint32_t abuf = sbase + bsel * SA_;
        const uint32_t bbuf = sbase + 2 * SA_ + bsel * SA_;
        const int ko = ch * 64;
#pragma unroll
        for (int u = 0; u < 4; u++) {
            CP_ASYNC16(abuf + ssto + u * 32 * SROW * 2, agp[u] + ko);
            CP_ASYNC16(bbuf + ssto + u * 32 * SROW * 2, bgp[u] + ko);
        }
        CP_COMMIT();
    };

    const uint32_t a_l = ((wm * 64 + (lane & 15)) * SROW + (lane >> 4) * 8) * 2;
    const uint32_t b_l = ((wn * 32 + (lane & 15)) * SROW + (lane >> 4) * 8) * 2;

    float acc[4][4][4];
#pragma unroll
    for (int i = 0; i < 4; i++)
#pragma unroll
        for (int j = 0; j < 4; j++)
#pragma unroll
            for (int r = 0; r < 4; r++) acc[i][j][r] = 0.f;

    load_chunk(0, 0);
    CP_WAIT0();
    __syncthreads();

    for (int ch = 0; ch < NCH_; ch++) {
        const int bsel = ch & 1;
        if (ch + 1 < NCH_) load_chunk(ch + 1, bsel ^ 1);

        const uint32_t abuf = sbase + bsel * SA_;
        const uint32_t bbuf = sbase + 2 * SA_ + bsel * SA_;
#pragma unroll
        for (int ks = 0; ks < 64; ks += 16) {
            uint32_t a[4][4];
#pragma unroll
            for (int mf = 0; mf < 4; mf++)
                LDSM_X4(a[mf][0], a[mf][1], a[mf][2], a[mf][3],
                        abuf + a_l + (mf * 16 * SROW + ks) * 2);
            uint32_t bq[2][4];
#pragma unroll
            for (int nf2 = 0; nf2 < 2; nf2++)
                LDSM_X4(bq[nf2][0], bq[nf2][1], bq[nf2][2], bq[nf2][3],
                        bbuf + b_l + (nf2 * 16 * SROW + ks) * 2);
#pragma unroll
            for (int mf = 0; mf < 4; mf++) {
#pragma unroll
                for (int nf = 0; nf < 4; nf++) {
                    const int h2 = nf >> 1, odd = nf & 1;
                    mma16816(acc[mf][nf], a[mf], bq[h2][odd], bq[h2][odd + 2]);
                }
            }
        }
        CP_WAIT0();
        __syncthreads();
    }

    // ---- epilogue ----
    const int rbase = row0 + wm * 64 + (lane >> 2);
    const int cbase = col0 + wn * 32 + (lane & 3) * 2;
#pragma unroll
    for (int mf = 0; mf < 4; mf++) {
#pragma unroll
        for (int half = 0; half < 2; half++) {
            const int m = rbase + mf * 16 + half * 8;
            if (m >= M_) continue;
            const int bi = m / N_, t = m - bi * N_;
#pragma unroll
            for (int nf = 0; nf < 4; nf++) {
                float v0 = acc[mf][nf][half * 2 + 0];
                float v1 = acc[mf][nf][half * 2 + 1];
                const int n0 = cbase + nf * 8;
                if (MODE == 0) {
                    const int which = col0 / C_;          // uniform per block
#pragma unroll
                    for (int j = 0; j < 2; j++) {
                        int nn = n0 + j;
                        int rem = nn - which * C_;
                        int h = rem >> 6, d = rem & 63;
                        float bias = (which == 0) ? p_qb[rem] : ((which == 2) ? p_vb[rem] : 0.f);
                        float val = ((j ? v1 : v0) + bias) * sscale[nn] + sshift[nn];
                        size_t off = (((size_t)(bi * H_ + h)) * N_ + t) * DH_ + d;
                        if (which == 0)      g_q[off] = val * QSCALE;
                        else if (which == 1) g_k[off] = val;
                        else                 g_v[off] = val;
                    }
                } else {
                    float* op = outp + (size_t)m * C_ + n0;
                    op[0] = (v0 + p_qb[n0])     * sscale[n0]     + sshift[n0];
                    op[1] = (v1 + p_qb[n0 + 1]) * sscale[n0 + 1] + sshift[n0 + 1];
                }
            }
        }
    }
}

// =====================================================================
// Kernel: attn[b,h] = softmax(q @ k^T + rel_bias) — 512 threads.
// Natural [token][64] smem layout, float4 inner loop (LDS.128):
// per d4-step: 4 broadcast q loads + 7 conflict-free k loads + 112 FMA.
// smem: ks[224][SKR] (rows 197.. zeroed) + qs[197][SKR] + tbl[732].
// =====================================================================
__global__ __launch_bounds__(512) void scores_kernel(
    const float* __restrict__ rel_table, const int* __restrict__ rel_index)
{
    extern __shared__ float sm[];
    float* ks  = sm;                     // [224][SKR]
    float* qs  = ks + 224 * SKR;         // [197][SKR]
    float* tbl = qs + N_ * SKR;          // [732]

    const int tid = threadIdx.x;
    const int bh = blockIdx.x;
    const int h = bh % H_;
    const float* kp = g_k + (size_t)bh * N_ * DH_;
    const float* qp = g_q + (size_t)bh * N_ * DH_;

    for (int idx = tid; idx < N_ * DH_; idx += 512) {
        int mm = idx >> 6, d = idx & 63;
        ks[mm * SKR + d] = kp[idx];
        qs[mm * SKR + d] = qp[idx];
    }
    for (int idx = tid; idx < (224 - N_) * DH_; idx += 512) {
        int mm = N_ + (idx >> 6), d = idx & 63;
        ks[mm * SKR + d] = 0.f;
    }
    for (int idx = tid; idx < NUM_REL_; idx += 512)
        tbl[idx] = rel_table[idx * H_ + h];
    __syncthreads();

    const int w = tid >> 5, l = tid & 31;
    float* outp = g_attn + (size_t)bh * NN_;

    for (int n0 = w * 4; n0 < N_; n0 += 64) {
        int nr[4];
#pragma unroll
        for (int r = 0; r < 4; r++) nr[r] = min(n0 + r, N_ - 1);
        float acc[4][7];
#pragma unroll
        for (int r = 0; r < 4; r++)
#pragma unroll
            for (int j = 0; j < 7; j++) acc[r][j] = 0.f;

#pragma unroll 4
        for (int d4 = 0; d4 < DH_; d4 += 4) {
            float4 q4[4];
#pragma unroll
            for (int r = 0; r < 4; r++)
                q4[r] = *(const float4*)&qs[nr[r] * SKR + d4];
#pragma unroll
            for (int j = 0; j < 7; j++) {
                float4 k4 = *(const float4*)&ks[(l + 32 * j) * SKR + d4];
#pragma unroll
                for (int r = 0; r < 4; r++) {
                    acc[r][j] = fmaf(q4[r].x, k4.x, acc[r][j]);
                    acc[r][j] = fmaf(q4[r].y, k4.y, acc[r][j]);
                    acc[r][j] = fmaf(q4[r].z, k4.z, acc[r][j]);
                    acc[r][j] = fmaf(q4[r].w, k4.w, acc[r][j]);
                }
            }
        }

#pragma unroll
        for (int r = 0; r < 4; r++) {
            int n = n0 + r;
            if (n >= N_) break;
            const int* ridx = rel_index + n * N_;
            float s[7];
#pragma unroll
            for (int j = 0; j < 7; j++) {
                int mm = l + 32 * j;
                s[j] = (mm < N_) ? acc[r][j] + tbl[ridx[mm]] : -1e30f;
            }
            float mx = s[0];
#pragma unroll
            for (int j = 1; j < 7; j++) mx = fmaxf(mx, s[j]);
#pragma unroll
            for (int o = 16; o; o >>= 1) mx = fmaxf(mx, __shfl_xor_sync(0xffffffffu, mx, o));
            float sum = 0.f;
#pragma unroll
            for (int j = 0; j < 7; j++) { float e = fast_expf(s[j] - mx); s[j] = e; sum += e; }
#pragma unroll
            for (int o = 16; o; o >>= 1) sum += __shfl_xor_sync(0xffffffffu, sum, o);
            float inv = 1.f / sum;
#pragma unroll
            for (int j = 0; j < 7; j++) {
                int mm = l + 32 * j;
                if (mm < N_) outp[(size_t)n * N_ + mm] = s[j] * inv;
            }
        }
    }
}

// =====================================================================
// Kernel: DCF head mix -> f32 g_attn2
// =====================================================================
__global__ __launch_bounds__(256) void mix_kernel(const float* __restrict__ coeff)
{
    __shared__ float mixs[12][13];
    const int tid = threadIdx.x;
    if (tid < 144) {
        int k = tid / 12, h = tid % 12;
        mixs[h][k] = coeff[k * 12 + h] + ((h == k) ? 1.f : 0.f);
    }
    __syncthreads();

    const int b = blockIdx.y;
    const int idx = blockIdx.x * 256 + tid;
    if (idx >= NN_) return;
    const float* ap = g_attn + (size_t)b * H_ * NN_ + idx;
    float a[12];
#pragma unroll
    for (int h = 0; h < 12; h++) a[h] = ap[(size_t)h * NN_];
    float* op = g_attn2 + (size_t)b * H_ * NN_ + idx;
#pragma unroll
    for (int k = 0; k < 12; k++) {
        float s = 0.f;
#pragma unroll
        for (int h = 0; h < 12; h++) s = fmaf(a[h], mixs[h][k], s);
        op[(size_t)k * NN_] = s;
    }
}

// =====================================================================
// Kernel: ctx = attn2 @ v (fp32, proven 64x64 tile). Epilogue writes
// ctx directly as packed split-bf16 into g_apack [hi,hi,lo].
// =====================================================================
__global__ __launch_bounds__(256) void av_gemm()
{
    __shared__ __align__(16) float As[16][68];
    __shared__ __align__(16) float Vs[16][68];
    const int tid = threadIdx.x;
    const int bh = blockIdx.y;
    const int row0 = blockIdx.x * 64;
    const float* A = g_attn2 + (size_t)bh * NN_;
    const float* V = g_v + (size_t)bh * N_ * DH_;
    const int tx = tid & 15, ty = tid >> 4;
    const int vr = tid >> 4;
    const int vc = (tid & 15) << 2;

    float acc[4][4];
#pragma unroll
    for (int i = 0; i < 4; i++)
#pragma unroll
        for (int j = 0; j < 4; j++) acc[i][j] = 0.f;

    for (int k0 = 0; k0 < N_; k0 += 16) {
#pragma unroll
        for (int u = 0; u < 4; u++) {
            int idx = tid + u * 256;
            int r = idx >> 4, kc = idx & 15;
            int n = row0 + r, k = k0 + kc;
            As[kc][r] = (n < N_ && k < N_) ? A[(size_t)n * N_ + k] : 0.f;
        }
        {
            int k = k0 + vr;
            float4 vv = (k < N_) ? *(const float4*)(V + (size_t)k * DH_ + vc)
                                 : make_float4(0.f, 0.f, 0.f, 0.f);
            *(float4*)&Vs[vr][vc] = vv;
        }
        __syncthreads();
#pragma unroll
        for (int kk = 0; kk < 16; kk++) {
            float4 av = *(const float4*)&As[kk][ty << 2];
            float4 bv = *(const float4*)&Vs[kk][tx << 2];
            float aa[4] = {av.x, av.y, av.z, av.w};
            float bb[4] = {bv.x, bv.y, bv.z, bv.w};
#pragma unroll
            for (int i = 0; i < 4; i++)
#pragma unroll
                for (int j = 0; j < 4; j++)
                    acc[i][j] = fmaf(aa[i], bb[j], acc[i][j]);
        }
        __syncthreads();
    }

    const int b = bh / H_, h = bh - b * H_;
#pragma unroll
    for (int i = 0; i < 4; i++) {
        int n = row0 + (ty << 2) + i;
        if (n < N_) {
            const size_t mrow = (size_t)(b * N_ + n) * KP_;
            const int c0 = h * DH_ + (tx << 2);
#pragma unroll
            for (int j = 0; j < 4; j++) {
                float val = acc[i][j];
                __nv_bfloat16 hi = __float2bfloat16(val);
                __nv_bfloat16 lo = __float2bfloat16(val - __bfloat162float(hi));
                int c = c0 + j;
                g_apack[mrow + c]           = hi;
                g_apack[mrow + C_ + c]      = hi;
                g_apack[mrow + 2 * C_ + c]  = lo;
            }
        }
    }
}

// =====================================================================
// Host launcher
// =====================================================================
extern "C" void kernel_launch(void* const* d_in, const int* in_sizes, int n_in,
                              void* d_out, int out_size)
{
    const float* x         = (const float*)d_in[0];
    const float* qkv_w     = (const float*)d_in[1];
    const float* q_bias    = (const float*)d_in[2];
    const float* v_bias    = (const float*)d_in[3];
    const float* ss_qkv    = (const float*)d_in[4];
    const float* sh_qkv    = (const float*)d_in[5];
    const float* rel_table = (const float*)d_in[6];
    const float* coeff     = (const float*)d_in[7];
    const float* proj_w    = (const float*)d_in[8];
    const float* proj_b    = (const float*)d_in[9];
    const float* ss_proj   = (const float*)d_in[10];
    const float* sh_proj   = (const float*)d_in[11];
    const int*   rel_index = (const int*)d_in[12];
    float* out = (float*)d_out;

    const int scores_smem = (224 * SKR + N_ * SKR + NUM_REL_) * 4;   // 117440
    cudaFuncSetAttribute(scores_kernel, cudaFuncAttributeMaxDynamicSharedMemorySize, scores_smem);
    const int gemm_smem = 4 * SA_;                                  // 73728
    cudaFuncSetAttribute(tc_gemm<0>, cudaFuncAttributeMaxDynamicSharedMemorySize, gemm_smem);
    cudaFuncSetAttribute(tc_gemm<1>, cudaFuncAttributeMaxDynamicSharedMemorySize, gemm_smem);

    __nv_bfloat16 *apack, *bqkv, *bproj;
    cudaGetSymbolAddress((void**)&apack, g_apack);
    cudaGetSymbolAddress((void**)&bqkv,  g_bqkv);
    cudaGetSymbolAddress((void**)&bproj, g_bproj);

    // 1) pack x and weights -> split bf16
    pack_a<<<(M_ * C_ + 255) / 256, 256>>>(x, apack, M_ * C_);
    pack_b<<<(3 * C_ * C_ + 255) / 256, 256>>>(qkv_w, bqkv, 3 * C_ * C_);
    pack_b<<<(C_ * C_ + 255) / 256, 256>>>(proj_w, bproj, C_ * C_);
    // 2) qkv GEMM + bias/SSF -> q,k,v (f32)
    tc_gemm<0><<<dim3(99, 18), 256, gemm_smem>>>(apack, bqkv, q_bias, v_bias,
                                                 ss_qkv, sh_qkv, nullptr);
    // 3) scores + softmax (float4 inner loop)
    scores_kernel<<<B_ * H_, 512, scores_smem>>>(rel_table, rel_index);
    // 4) head mix (f32)
    mix_kernel<<<dim3((NN_ + 255) / 256, B_), 256>>>(coeff);
    // 5) attn2 @ v -> packed ctx directly into g_apack
    av_gemm<<<dim3(4, B_ * H_), 256>>>();
    // 6) proj GEMM
    tc_gemm<1><<<dim3(99, 6), 256, gemm_smem>>>(apack, bproj, proj_b, nullptr,
                                                ss_proj, sh_proj, out);
}

// round 13
// speedup vs baseline: 1.2511x; 1.2511x over previous
#include <cuda_runtime.h>
#include <cuda_fp16.h>
#include <cuda_bf16.h>
#include <cstdint>

#define B_ 64
#define N_ 197
#define C_ 768
#define H_ 12
#define DH_ 64
#define M_ (B_*N_)          // 12608
#define NN_ (N_*N_)         // 38809
#define NUM_REL_ 732
#define QSCALE 0.125f
#define KTP 224
#define KP_ 1536            // packed K = 2*768 (2-term fp16 split)
#define NCH_ 24             // K chunks of 64 fp16
#define SROW 72             // smem row stride in fp16 (64 + 8 pad)
#define SA_ (128*SROW*2)    // one smem tile: 18432 bytes

// ---------------- scratch ----------------
__device__ float g_q[(size_t)B_*H_*N_*DH_];
__device__ float g_k[(size_t)B_*H_*N_*DH_];
__device__ float g_v[(size_t)B_*H_*N_*DH_];
__device__ float g_attn [(size_t)B_*H_*NN_];
__device__ float g_attn2[(size_t)B_*H_*NN_];
__device__ __half g_apack[(size_t)M_*KP_];     // packed activations [hi, lo]
__device__ __half g_bqkv [(size_t)3*C_*KP_];   // packed qkv weights [hi, hi]
__device__ __half g_bproj[(size_t)C_*KP_];     // packed proj weights [hi, hi]

// ---------------- PTX helpers (baseline ISA only) ----------------
__device__ __forceinline__ uint32_t smem_to_u32(const void* p) {
    uint32_t a;
    asm("{ .reg .u64 t; cvta.to.shared.u64 t, %1; cvt.u32.u64 %0, t; }" : "=r"(a) : "l"(p));
    return a;
}
#define CP_ASYNC16(sm, gp) \
    asm volatile("cp.async.cg.shared.global [%0], [%1], 16;" :: "r"(sm), "l"(gp))
#define CP_COMMIT()  asm volatile("cp.async.commit_group;" ::: "memory")
#define CP_WAIT0()   asm volatile("cp.async.wait_group 0;" ::: "memory")
#define LDSM_X4(r0,r1,r2,r3, addr) \
    asm volatile("ldmatrix.sync.aligned.m8n8.x4.shared.b16 {%0,%1,%2,%3}, [%4];" \
        : "=r"(r0), "=r"(r1), "=r"(r2), "=r"(r3) : "r"(addr))

__device__ __forceinline__ void mma16816(float* c, const uint32_t* a, uint32_t b0, uint32_t b1) {
    asm volatile("mma.sync.aligned.m16n8k16.row.col.f32.f16.f16.f32 "
        "{%0,%1,%2,%3}, {%4,%5,%6,%7}, {%8,%9}, {%0,%1,%2,%3};"
        : "+f"(c[0]), "+f"(c[1]), "+f"(c[2]), "+f"(c[3])
        : "r"(a[0]), "r"(a[1]), "r"(a[2]), "r"(a[3]), "r"(b0), "r"(b1));
}

// =====================================================================
// Pack kernels: f32 -> 2-term fp16 split along packed K (KP_ = 2*C)
// A: [hi, lo] (exact split);  B: [hi, hi]  =>  A.B = a_hi*b_hi + a_lo*b_hi = a*b_hi
// =====================================================================
__global__ __launch_bounds__(256) void pack_a(const float* __restrict__ src,
                                              __half* __restrict__ dst, int total)
{
    int idx = blockIdx.x * 256 + threadIdx.x;
    if (idx >= total) return;
    int row = idx / C_, k = idx - row * C_;
    float v = src[idx];
    __half hi = __float2half(v);
    __half lo = __float2half(v - __half2float(hi));
    size_t ro = (size_t)row * KP_;
    dst[ro + k] = hi; dst[ro + C_ + k] = lo;
}
__global__ __launch_bounds__(256) void pack_b(const float* __restrict__ src,
                                              __half* __restrict__ dst, int total)
{
    int idx = blockIdx.x * 256 + threadIdx.x;
    if (idx >= total) return;
    int row = idx / C_, k = idx - row * C_;
    __half hi = __float2half(src[idx]);
    size_t ro = (size_t)row * KP_;
    dst[ro + k] = hi; dst[ro + C_ + k] = hi;
}

// =====================================================================
// mma.sync GEMM (proven shape): block 128x128, 8 warps (2Mx4N),
// warp tile 64x32, BK=64, double-buffered cp.async, 2 CTAs/SM.
// MODE 0: qkv epilogue (q,k,v -> f32); MODE 1: proj epilogue -> out.
// =====================================================================
template<int MODE>
__global__ __launch_bounds__(256) void tc_gemm(
    const __half* __restrict__ Ap, const __half* __restrict__ Bp,
    const float* __restrict__ p_qb, const float* __restrict__ p_vb,
    const float* __restrict__ sscale, const float* __restrict__ sshift,
    float* __restrict__ outp)
{
    extern __shared__ char smem_raw[];
    const uint32_t sbase = smem_to_u32(smem_raw);
    const int tid = threadIdx.x;
    const int lane = tid & 31, wid = tid >> 5;
    const int wm = wid & 1;
    const int wn = wid >> 1;
    const int row0 = blockIdx.x * 128;
    const int col0 = blockIdx.y * 128;

    const int lcol = tid & 7;
    const int lrow = tid >> 3;
    const __half* agp[4];
    const __half* bgp[4];
#pragma unroll
    for (int u = 0; u < 4; u++) {
        int ar = min(row0 + lrow + u * 32, M_ - 1);
        agp[u] = Ap + (size_t)ar * KP_ + lcol * 8;
        bgp[u] = Bp + (size_t)(col0 + lrow + u * 32) * KP_ + lcol * 8;
    }
    const uint32_t ssto = (uint32_t)((lrow * SROW + lcol * 8) * 2);

    auto load_chunk = [&](int ch, int bsel) {
        const uint32_t abuf = sbase + bsel * SA_;
        const uint32_t bbuf = sbase + 2 * SA_ + bsel * SA_;
        const int ko = ch * 64;
#pragma unroll
        for (int u = 0; u < 4; u++) {
            CP_ASYNC16(abuf + ssto + u * 32 * SROW * 2, agp[u] + ko);
            CP_ASYNC16(bbuf + ssto + u * 32 * SROW * 2, bgp[u] + ko);
        }
        CP_COMMIT();
    };

    const uint32_t a_l = ((wm * 64 + (lane & 15)) * SROW + (lane >> 4) * 8) * 2;
    const uint32_t b_l = ((wn * 32 + (lane & 15)) * SROW + (lane >> 4) * 8) * 2;

    float acc[4][4][4];
#pragma unroll
    for (int i = 0; i < 4; i++)
#pragma unroll
        for (int j = 0; j < 4; j++)
#pragma unroll
            for (int r = 0; r < 4; r++) acc[i][j][r] = 0.f;

    load_chunk(0, 0);
    CP_WAIT0();
    __syncthreads();

    for (int ch = 0; ch < NCH_; ch++) {
        const int bsel = ch & 1;
        if (ch + 1 < NCH_) load_chunk(ch + 1, bsel ^ 1);

        const uint32_t abuf = sbase + bsel * SA_;
        const uint32_t bbuf = sbase + 2 * SA_ + bsel * SA_;
#pragma unroll
        for (int ks = 0; ks < 64; ks += 16) {
            uint32_t a[4][4];
#pragma unroll
            for (int mf = 0; mf < 4; mf++)
                LDSM_X4(a[mf][0], a[mf][1], a[mf][2], a[mf][3],
                        abuf + a_l + (mf * 16 * SROW + ks) * 2);
            uint32_t bq[2][4];
#pragma unroll
            for (int nf2 = 0; nf2 < 2; nf2++)
                LDSM_X4(bq[nf2][0], bq[nf2][1], bq[nf2][2], bq[nf2][3],
                        bbuf + b_l + (nf2 * 16 * SROW + ks) * 2);
#pragma unroll
            for (int mf = 0; mf < 4; mf++) {
#pragma unroll
                for (int nf = 0; nf < 4; nf++) {
                    const int h2 = nf >> 1, odd = nf & 1;
                    mma16816(acc[mf][nf], a[mf], bq[h2][odd], bq[h2][odd + 2]);
                }
            }
        }
        CP_WAIT0();
        __syncthreads();
    }

    // ---- epilogue ----
    const int rbase = row0 + wm * 64 + (lane >> 2);
    const int cbase = col0 + wn * 32 + (lane & 3) * 2;
#pragma unroll
    for (int mf = 0; mf < 4; mf++) {
#pragma unroll
        for (int half = 0; half < 2; half++) {
            const int m = rbase + mf * 16 + half * 8;
            if (m >= M_) continue;
            const int bi = m / N_, t = m - bi * N_;
#pragma unroll
            for (int nf = 0; nf < 4; nf++) {
                float v0 = acc[mf][nf][half * 2 + 0];
                float v1 = acc[mf][nf][half * 2 + 1];
                const int n0 = cbase + nf * 8;
                if (MODE == 0) {
                    const int which = col0 / C_;          // uniform per block
#pragma unroll
                    for (int j = 0; j < 2; j++) {
                        int nn = n0 + j;
                        int rem = nn - which * C_;
                        int h = rem >> 6, d = rem & 63;
                        float bias = (which == 0) ? p_qb[rem] : ((which == 2) ? p_vb[rem] : 0.f);
                        float val = ((j ? v1 : v0) + bias) * sscale[nn] + sshift[nn];
                        size_t off = (((size_t)(bi * H_ + h)) * N_ + t) * DH_ + d;
                        if (which == 0)      g_q[off] = val * QSCALE;
                        else if (which == 1) g_k[off] = val;
                        else                 g_v[off] = val;
                    }
                } else {
                    float* op = outp + (size_t)m * C_ + n0;
                    op[0] = (v0 + p_qb[n0])     * sscale[n0]     + sshift[n0];
                    op[1] = (v1 + p_qb[n0 + 1]) * sscale[n0 + 1] + sshift[n0 + 1];
                }
            }
        }
    }
}

// =====================================================================
// Kernel: attn[b,h] = softmax(q @ k^T + rel_bias) — R9-proven form:
// 512 threads, kT transposed layout, __expf.
// =====================================================================
__global__ __launch_bounds__(512) void scores_kernel(
    const float* __restrict__ rel_table, const int* __restrict__ rel_index)
{
    extern __shared__ float sm[];
    float* kT  = sm;
    float* qs  = kT + 64 * KTP;
    float* tbl = qs + N_ * DH_;

    const int tid = threadIdx.x;
    const int bh = blockIdx.x;
    const int h = bh % H_;
    const float* kp = g_k + (size_t)bh * N_ * DH_;
    const float* qp = g_q + (size_t)bh * N_ * DH_;

    for (int idx = tid; idx < N_ * DH_; idx += 512) {
        int mm = idx >> 6, d = idx & 63;
        kT[d * KTP + mm] = kp[idx];
        qs[idx] = qp[idx];
    }
    for (int idx = tid; idx < 64 * (KTP - N_); idx += 512) {
        int d = idx / (KTP - N_), mm = N_ + idx % (KTP - N_);
        kT[d * KTP + mm] = 0.f;
    }
    for (int idx = tid; idx < NUM_REL_; idx += 512)
        tbl[idx] = rel_table[idx * H_ + h];
    __syncthreads();

    const int w = tid >> 5, l = tid & 31;
    float* outp = g_attn + (size_t)bh * NN_;

    for (int n0 = w * 4; n0 < N_; n0 += 64) {
        int nr[4];
#pragma unroll
        for (int r = 0; r < 4; r++) nr[r] = min(n0 + r, N_ - 1);
        float acc[4][7];
#pragma unroll
        for (int r = 0; r < 4; r++)
#pragma unroll
            for (int j = 0; j < 7; j++) acc[r][j] = 0.f;

#pragma unroll 4
        for (int d = 0; d < DH_; d++) {
            float qv[4];
#pragma unroll
            for (int r = 0; r < 4; r++) qv[r] = qs[nr[r] * 64 + d];
#pragma unroll
            for (int j = 0; j < 7; j++) {
                float kv = kT[d * KTP + l + 32 * j];
#pragma unroll
                for (int r = 0; r < 4; r++) acc[r][j] = fmaf(qv[r], kv, acc[r][j]);
            }
        }

#pragma unroll
        for (int r = 0; r < 4; r++) {
            int n = n0 + r;
            if (n >= N_) break;
            const int* ridx = rel_index + n * N_;
            float s[7];
#pragma unroll
            for (int j = 0; j < 7; j++) {
                int mm = l + 32 * j;
                s[j] = (mm < N_) ? acc[r][j] + tbl[ridx[mm]] : -1e30f;
            }
            float mx = s[0];
#pragma unroll
            for (int j = 1; j < 7; j++) mx = fmaxf(mx, s[j]);
#pragma unroll
            for (int o = 16; o; o >>= 1) mx = fmaxf(mx, __shfl_xor_sync(0xffffffffu, mx, o));
            float sum = 0.f;
#pragma unroll
            for (int j = 0; j < 7; j++) { float e = __expf(s[j] - mx); s[j] = e; sum += e; }
#pragma unroll
            for (int o = 16; o; o >>= 1) sum += __shfl_xor_sync(0xffffffffu, sum, o);
            float inv = 1.f / sum;
#pragma unroll
            for (int j = 0; j < 7; j++) {
                int mm = l + 32 * j;
                if (mm < N_) outp[(size_t)n * N_ + mm] = s[j] * inv;
            }
        }
    }
}

// =====================================================================
// Kernel: DCF head mix -> f32 g_attn2
// =====================================================================
__global__ __launch_bounds__(256) void mix_kernel(const float* __restrict__ coeff)
{
    __shared__ float mixs[12][13];
    const int tid = threadIdx.x;
    if (tid < 144) {
        int k = tid / 12, h = tid % 12;
        mixs[h][k] = coeff[k * 12 + h] + ((h == k) ? 1.f : 0.f);
    }
    __syncthreads();

    const int b = blockIdx.y;
    const int idx = blockIdx.x * 256 + tid;
    if (idx >= NN_) return;
    const float* ap = g_attn + (size_t)b * H_ * NN_ + idx;
    float a[12];
#pragma unroll
    for (int h = 0; h < 12; h++) a[h] = ap[(size_t)h * NN_];
    float* op = g_attn2 + (size_t)b * H_ * NN_ + idx;
#pragma unroll
    for (int k = 0; k < 12; k++) {
        float s = 0.f;
#pragma unroll
        for (int h = 0; h < 12; h++) s = fmaf(a[h], mixs[h][k], s);
        op[(size_t)k * NN_] = s;
    }
}

// =====================================================================
// Kernel: ctx = attn2 @ v (fp32, proven 64x64 tile). Epilogue writes
// ctx directly as 2-term fp16 split into g_apack [hi, lo].
// =====================================================================
__global__ __launch_bounds__(256) void av_gemm()
{
    __shared__ __align__(16) float As[16][68];
    __shared__ __align__(16) float Vs[16][68];
    const int tid = threadIdx.x;
    const int bh = blockIdx.y;
    const int row0 = blockIdx.x * 64;
    const float* A = g_attn2 + (size_t)bh * NN_;
    const float* V = g_v + (size_t)bh * N_ * DH_;
    const int tx = tid & 15, ty = tid >> 4;
    const int vr = tid >> 4;
    const int vc = (tid & 15) << 2;

    float acc[4][4];
#pragma unroll
    for (int i = 0; i < 4; i++)
#pragma unroll
        for (int j = 0; j < 4; j++) acc[i][j] = 0.f;

    for (int k0 = 0; k0 < N_; k0 += 16) {
#pragma unroll
        for (int u = 0; u < 4; u++) {
            int idx = tid + u * 256;
            int r = idx >> 4, kc = idx & 15;
            int n = row0 + r, k = k0 + kc;
            As[kc][r] = (n < N_ && k < N_) ? A[(size_t)n * N_ + k] : 0.f;
        }
        {
            int k = k0 + vr;
            float4 vv = (k < N_) ? *(const float4*)(V + (size_t)k * DH_ + vc)
                                 : make_float4(0.f, 0.f, 0.f, 0.f);
            *(float4*)&Vs[vr][vc] = vv;
        }
        __syncthreads();
#pragma unroll
        for (int kk = 0; kk < 16; kk++) {
            float4 av = *(const float4*)&As[kk][ty << 2];
            float4 bv = *(const float4*)&Vs[kk][tx << 2];
            float aa[4] = {av.x, av.y, av.z, av.w};
            float bb[4] = {bv.x, bv.y, bv.z, bv.w};
#pragma unroll
            for (int i = 0; i < 4; i++)
#pragma unroll
                for (int j = 0; j < 4; j++)
                    acc[i][j] = fmaf(aa[i], bb[j], acc[i][j]);
        }
        __syncthreads();
    }

    const int b = bh / H_, h = bh - b * H_;
#pragma unroll
    for (int i = 0; i < 4; i++) {
        int n = row0 + (ty << 2) + i;
        if (n < N_) {
            const size_t mrow = (size_t)(b * N_ + n) * KP_;
            const int c0 = h * DH_ + (tx << 2);
#pragma unroll
            for (int j = 0; j < 4; j++) {
                float val = acc[i][j];
                __half hi = __float2half(val);
                __half lo = __float2half(val - __half2float(hi));
                int c = c0 + j;
                g_apack[mrow + c]       = hi;
                g_apack[mrow + C_ + c]  = lo;
            }
        }
    }
}

// =====================================================================
// Host launcher
// =====================================================================
extern "C" void kernel_launch(void* const* d_in, const int* in_sizes, int n_in,
                              void* d_out, int out_size)
{
    const float* x         = (const float*)d_in[0];
    const float* qkv_w     = (const float*)d_in[1];
    const float* q_bias    = (const float*)d_in[2];
    const float* v_bias    = (const float*)d_in[3];
    const float* ss_qkv    = (const float*)d_in[4];
    const float* sh_qkv    = (const float*)d_in[5];
    const float* rel_table = (const float*)d_in[6];
    const float* coeff     = (const float*)d_in[7];
    const float* proj_w    = (const float*)d_in[8];
    const float* proj_b    = (const float*)d_in[9];
    const float* ss_proj   = (const float*)d_in[10];
    const float* sh_proj   = (const float*)d_in[11];
    const int*   rel_index = (const int*)d_in[12];
    float* out = (float*)d_out;

    const int scores_smem = (64 * KTP + N_ * DH_ + NUM_REL_) * 4;   // 110704
    cudaFuncSetAttribute(scores_kernel, cudaFuncAttributeMaxDynamicSharedMemorySize, scores_smem);
    const int gemm_smem = 4 * SA_;                                  // 73728
    cudaFuncSetAttribute(tc_gemm<0>, cudaFuncAttributeMaxDynamicSharedMemorySize, gemm_smem);
    cudaFuncSetAttribute(tc_gemm<1>, cudaFuncAttributeMaxDynamicSharedMemorySize, gemm_smem);

    __half *apack, *bqkv, *bproj;
    cudaGetSymbolAddress((void**)&apack, g_apack);
    cudaGetSymbolAddress((void**)&bqkv,  g_bqkv);
    cudaGetSymbolAddress((void**)&bproj, g_bproj);

    // 1) pack x and weights -> 2-term fp16 split
    pack_a<<<(M_ * C_ + 255) / 256, 256>>>(x, apack, M_ * C_);
    pack_b<<<(3 * C_ * C_ + 255) / 256, 256>>>(qkv_w, bqkv, 3 * C_ * C_);
    pack_b<<<(C_ * C_ + 255) / 256, 256>>>(proj_w, bproj, C_ * C_);
    // 2) qkv GEMM + bias/SSF -> q,k,v (f32)
    tc_gemm<0><<<dim3(99, 18), 256, gemm_smem>>>(apack, bqkv, q_bias, v_bias,
                                                 ss_qkv, sh_qkv, nullptr);
    // 3) scores + softmax
    scores_kernel<<<B_ * H_, 512, scores_smem>>>(rel_table, rel_index);
    // 4) head mix (f32)
    mix_kernel<<<dim3((NN_ + 255) / 256, B_), 256>>>(coeff);
    // 5) attn2 @ v -> packed ctx directly into g_apack
    av_gemm<<<dim3(4, B_ * H_), 256>>>();
    // 6) proj GEMM
    tc_gemm<1><<<dim3(99, 6), 256, gemm_smem>>>(apack, bproj, proj_b, nullptr,
                                                ss_proj, sh_proj, out);
}